// round 2
// baseline (speedup 1.0000x reference)
#include <cuda_runtime.h>
#include <cuda_bf16.h>
#include <cstdint>

#define C_DIM   128
#define HW      1024
#define BN_TOT  32      // 8 batches * 4 views
#define EPSF    1e-8f

#define BM   128
#define BN   64
#define KC   32
#define KPAD 36

// Scratch: normalized feature maps split into bf16 hi/lo parts, layout [view][c][p]
__device__ __nv_bfloat16 g_hi[BN_TOT * C_DIM * HW];
__device__ __nv_bfloat16 g_lo[BN_TOT * C_DIM * HW];

// ---------------------------------------------------------------------------
// Kernel 1: per-pixel channel L2 normalization + bf16 hi/lo split
// one thread per (view, pixel); 32*1024 = 32768 threads
// ---------------------------------------------------------------------------
__global__ void norm_split_kernel(const float* __restrict__ x) {
    int idx = blockIdx.x * blockDim.x + threadIdx.x;
    int bn = idx >> 10;          // view index 0..31
    int p  = idx & 1023;         // pixel 0..1023
    const float* xp = x + (size_t)bn * (C_DIM * HW) + p;

    float s = 0.f;
#pragma unroll 8
    for (int c = 0; c < C_DIM; ++c) {
        float v = xp[c << 10];
        s += v * v;
    }
    float inv = 1.f / (sqrtf(s) + EPSF);

    size_t base = (size_t)bn * (C_DIM * HW) + p;
#pragma unroll 8
    for (int c = 0; c < C_DIM; ++c) {
        float v = xp[c << 10] * inv;
        __nv_bfloat16 h = __float2bfloat16(v);
        float rem = v - __bfloat162float(h);
        g_hi[base + (c << 10)] = h;
        g_lo[base + (c << 10)] = __float2bfloat16(rem);
    }
}

// ---------------------------------------------------------------------------
// Kernel 2: corr[pr] = A^T B  (A = F_j, B = F_i, both (C=128, HW) K-major)
// block tile: 128 (p) x 64 (q); 8 warps in 4x2 grid, each warp 32x32
// mma.sync m16n8k16 bf16, split accumulation: hi*hi + hi*lo + lo*hi
// ---------------------------------------------------------------------------
#define MMA_BF16(d, a, bb)                                                   \
    asm volatile(                                                            \
        "mma.sync.aligned.m16n8k16.row.col.f32.bf16.bf16.f32 "               \
        "{%0,%1,%2,%3}, {%4,%5,%6,%7}, {%8,%9}, {%0,%1,%2,%3};\n"            \
        : "+f"((d)[0]), "+f"((d)[1]), "+f"((d)[2]), "+f"((d)[3])             \
        : "r"((a)[0]), "r"((a)[1]), "r"((a)[2]), "r"((a)[3]),                \
          "r"((bb)[0]), "r"((bb)[1]))

__global__ __launch_bounds__(256, 2) void corr_gemm_kernel(float* __restrict__ out) {
    __shared__ __nv_bfloat16 As[2][BM][KPAD];   // [hi/lo][m=p][k=c]
    __shared__ __nv_bfloat16 Bs[2][BN][KPAD];   // [hi/lo][n=q][k=c]

    const int tid = threadIdx.x;
    const int pr  = blockIdx.z;                 // 0..95
    const int b   = pr / 12;
    const int r   = pr % 12;
    const int i   = r / 3;
    const int k   = r % 3;
    const int j   = k + (k >= i ? 1 : 0);       // jj[i][k]

    const __nv_bfloat16* Ahi = g_hi + (size_t)(b * 4 + j) * (C_DIM * HW);
    const __nv_bfloat16* Alo = g_lo + (size_t)(b * 4 + j) * (C_DIM * HW);
    const __nv_bfloat16* Bhi = g_hi + (size_t)(b * 4 + i) * (C_DIM * HW);
    const __nv_bfloat16* Blo = g_lo + (size_t)(b * 4 + i) * (C_DIM * HW);

    const int p0 = blockIdx.y * BM;
    const int q0 = blockIdx.x * BN;

    const int w  = tid >> 5;
    const int wm = w >> 1;      // 0..3
    const int wn = w & 1;       // 0..1
    const int l  = tid & 31;
    const int g  = l >> 2;      // group id 0..7
    const int tg = l & 3;       // thread-in-group 0..3

    float acc[2][4][4];
#pragma unroll
    for (int mt = 0; mt < 2; ++mt)
#pragma unroll
        for (int nt = 0; nt < 4; ++nt)
#pragma unroll
            for (int e = 0; e < 4; ++e) acc[mt][nt][e] = 0.f;

    for (int kc = 0; kc < C_DIM; kc += KC) {
        // ---- global -> shared (transpose c-major -> [m][k]) ----
#pragma unroll
        for (int t = tid; t < BM * KC; t += 256) {
            int kk = t >> 7;            // 0..31
            int pm = t & 127;           // 0..127  (contiguous -> coalesced reads)
            size_t go = (size_t)(kc + kk) * HW + p0 + pm;
            As[0][pm][kk] = Ahi[go];
            As[1][pm][kk] = Alo[go];
        }
#pragma unroll
        for (int t = tid; t < BN * KC; t += 256) {
            int kk = t >> 6;            // 0..31
            int qm = t & 63;            // 0..63
            size_t go = (size_t)(kc + kk) * HW + q0 + qm;
            Bs[0][qm][kk] = Bhi[go];
            Bs[1][qm][kk] = Blo[go];
        }
        __syncthreads();

#pragma unroll
        for (int ks = 0; ks < KC; ks += 16) {
            uint32_t a_hi[2][4], a_lo[2][4];
#pragma unroll
            for (int mt = 0; mt < 2; ++mt) {
                int row = wm * 32 + mt * 16 + g;
                a_hi[mt][0] = *(const uint32_t*)&As[0][row    ][ks + tg * 2    ];
                a_hi[mt][1] = *(const uint32_t*)&As[0][row + 8][ks + tg * 2    ];
                a_hi[mt][2] = *(const uint32_t*)&As[0][row    ][ks + tg * 2 + 8];
                a_hi[mt][3] = *(const uint32_t*)&As[0][row + 8][ks + tg * 2 + 8];
                a_lo[mt][0] = *(const uint32_t*)&As[1][row    ][ks + tg * 2    ];
                a_lo[mt][1] = *(const uint32_t*)&As[1][row + 8][ks + tg * 2    ];
                a_lo[mt][2] = *(const uint32_t*)&As[1][row    ][ks + tg * 2 + 8];
                a_lo[mt][3] = *(const uint32_t*)&As[1][row + 8][ks + tg * 2 + 8];
            }
            uint32_t b_hi[4][2], b_lo[4][2];
#pragma unroll
            for (int nt = 0; nt < 4; ++nt) {
                int col = wn * 32 + nt * 8 + g;
                b_hi[nt][0] = *(const uint32_t*)&Bs[0][col][ks + tg * 2    ];
                b_hi[nt][1] = *(const uint32_t*)&Bs[0][col][ks + tg * 2 + 8];
                b_lo[nt][0] = *(const uint32_t*)&Bs[1][col][ks + tg * 2    ];
                b_lo[nt][1] = *(const uint32_t*)&Bs[1][col][ks + tg * 2 + 8];
            }
#pragma unroll
            for (int mt = 0; mt < 2; ++mt) {
#pragma unroll
                for (int nt = 0; nt < 4; ++nt) {
                    MMA_BF16(acc[mt][nt], a_hi[mt], b_hi[nt]);
                    MMA_BF16(acc[mt][nt], a_hi[mt], b_lo[nt]);
                    MMA_BF16(acc[mt][nt], a_lo[mt], b_hi[nt]);
                }
            }
        }
        __syncthreads();
    }

    // ---- epilogue: fp32 stores, float2 per (row, col pair) ----
    float* op = out + (size_t)pr * (HW * HW);
#pragma unroll
    for (int mt = 0; mt < 2; ++mt) {
#pragma unroll
        for (int nt = 0; nt < 4; ++nt) {
            int row = p0 + wm * 32 + mt * 16 + g;
            int col = q0 + wn * 32 + nt * 8 + tg * 2;
            float2 v0 = make_float2(acc[mt][nt][0], acc[mt][nt][1]);
            float2 v1 = make_float2(acc[mt][nt][2], acc[mt][nt][3]);
            *(float2*)&op[(size_t)row * HW + col]       = v0;
            *(float2*)&op[(size_t)(row + 8) * HW + col] = v1;
        }
    }
}

// ---------------------------------------------------------------------------
extern "C" void kernel_launch(void* const* d_in, const int* in_sizes, int n_in,
                              void* d_out, int out_size) {
    const float* x = (const float*)d_in[0];
    float* out = (float*)d_out;

    norm_split_kernel<<<(BN_TOT * HW) / 256, 256>>>(x);

    dim3 grid(HW / BN, HW / BM, 96);   // (16, 8, 96)
    corr_gemm_kernel<<<grid, 256>>>(out);
}

// round 5
// speedup vs baseline: 2.0591x; 2.0591x over previous
#include <cuda_runtime.h>
#include <cuda_bf16.h>
#include <cstdint>

#define HW   1024
#define CD   128
#define EPSF 1e-8f

// Normalized features, bf16 hi/lo split, pixel-major:
// g_feat[view][p][0..127]=hi, [128..255]=lo   (512 B per pixel row)
__device__ __nv_bfloat16 g_feat[32 * HW * 256];

// ---------------------------------------------------------------------------
__device__ __forceinline__ uint32_t smem_u32(const void* p) {
    uint32_t a;
    asm("{ .reg .u64 t; cvta.to.shared.u64 t, %1; cvt.u32.u64 %0, t; }" : "=r"(a) : "l"(p));
    return a;
}

#define CP_ASYNC(s, g) \
    asm volatile("cp.async.cg.shared.global [%0], [%1], 16;" :: "r"(s), "l"(g))
#define CP_COMMIT() asm volatile("cp.async.commit_group;" ::: "memory")
#define CP_WAIT0()  asm volatile("cp.async.wait_group 0;" ::: "memory")

#define LDSM4(r, a) \
    asm volatile("ldmatrix.sync.aligned.m8n8.x4.shared.b16 {%0,%1,%2,%3}, [%4];" \
        : "=r"((r)[0]), "=r"((r)[1]), "=r"((r)[2]), "=r"((r)[3]) : "r"(a))

#define MMA(d, a, b0v, b1v)                                                  \
    asm volatile(                                                            \
        "mma.sync.aligned.m16n8k16.row.col.f32.bf16.bf16.f32 "               \
        "{%0,%1,%2,%3}, {%4,%5,%6,%7}, {%8,%9}, {%0,%1,%2,%3};\n"            \
        : "+f"((d)[0]), "+f"((d)[1]), "+f"((d)[2]), "+f"((d)[3])             \
        : "r"((a)[0]), "r"((a)[1]), "r"((a)[2]), "r"((a)[3]),                \
          "r"(b0v), "r"(b1v))

// ---------------------------------------------------------------------------
// Kernel 1: L2-normalize per pixel, split to bf16 hi/lo, write pixel-major
// ---------------------------------------------------------------------------
__global__ __launch_bounds__(256) void norm_split_kernel(const float* __restrict__ x) {
    __shared__ uint32_t tile[8][33 * 32];
    int w = threadIdx.x >> 5, l = threadIdx.x & 31;
    int gp = blockIdx.x * 256 + w * 32 + l;        // global pixel over 32 views
    int view = gp >> 10, p = gp & 1023;
    const float* xp = x + (size_t)view * (CD * HW) + p;

    float s = 0.f;
#pragma unroll 8
    for (int c = 0; c < CD; ++c) { float v = xp[c << 10]; s += v * v; }
    float inv = 1.f / (sqrtf(s) + EPSF);

    __nv_bfloat16* ob = g_feat + (size_t)(gp - l) * 256;   // warp's base pixel row

    for (int cb = 0; cb < 4; ++cb) {
#pragma unroll
        for (int ci = 0; ci < 32; ++ci) {
            float v = xp[(cb * 32 + ci) << 10] * inv;
            __nv_bfloat16 h = __float2bfloat16(v);
            __nv_bfloat16 lo = __float2bfloat16(v - __bfloat162float(h));
            tile[w][ci * 33 + l] = (uint32_t)__bfloat16_as_ushort(h)
                                 | ((uint32_t)__bfloat16_as_ushort(lo) << 16);
        }
        __syncwarp();
#pragma unroll
        for (int rr = 0; rr < 32; ++rr) {
            uint32_t v = tile[w][l * 33 + rr];
            __nv_bfloat16* row = ob + (size_t)rr * 256 + cb * 32 + l;
            row[0]   = __ushort_as_bfloat16((unsigned short)(v & 0xFFFF));
            row[128] = __ushort_as_bfloat16((unsigned short)(v >> 16));
        }
        __syncwarp();
    }
}

// ---------------------------------------------------------------------------
// Kernel 2: HMMA GEMM, CTA tile 128x128, warp tile 64x32, K pipelined.
// Smem stage (32KB): [A_hi 8K][A_lo 8K][B_hi 8K][B_lo 8K], each half-tile
// 128 rows x 32 k (64B rows, 4 x 16B chunks, chunk swizzle ch^((row>>1)&3)).
// 2 stages double-buffered via cp.async. 3-term split: hh + lh + hl.
// ---------------------------------------------------------------------------
#define STAGE_B 32768

__global__ __launch_bounds__(256, 2) void corr_gemm2(float* __restrict__ out) {
    extern __shared__ char smem[];
    uint32_t sb = smem_u32(smem);
    const int tid = threadIdx.x;
    const int w = tid >> 5, l = tid & 31;
    const int wm = w >> 2, wn = w & 3;          // warp grid 2x4
    const int lo16 = l & 15, hi2 = l >> 4;

    const int q0 = blockIdx.x * 128;
    const int p0 = blockIdx.y * 128;
    const int pr = blockIdx.z;
    const int b = pr / 12, r = pr % 12, i = r / 3, k3 = r % 3;
    const int j = k3 + (k3 >= i ? 1 : 0);

    const char* Af = (const char*)g_feat + (size_t)(b * 4 + j) * HW * 512 + (size_t)p0 * 512;
    const char* Bf = (const char*)g_feat + (size_t)(b * 4 + i) * HW * 512 + (size_t)q0 * 512;

    float acc[4][4][4];
#pragma unroll
    for (int mt = 0; mt < 4; ++mt)
#pragma unroll
        for (int nt = 0; nt < 4; ++nt)
#pragma unroll
            for (int e = 0; e < 4; ++e) acc[mt][nt][e] = 0.f;

    // ---- stage loader: 2048 16B chunks (A+B, hi+lo), 8 per thread ----
    auto load_stage = [&](int kc, int st) {
        uint32_t sbase = sb + st * STAGE_B;
        const char* As = Af + kc * 64;
        const char* Bs = Bf + kc * 64;
#pragma unroll
        for (int it = 0; it < 4; ++it) {
            int c = it * 256 + tid;
            int m = c >> 3, half = (c >> 2) & 1, ch = c & 3;
            uint32_t soff = half * 8192u + (uint32_t)((m * 4 + (ch ^ ((m >> 1) & 3))) << 4);
            const char* g = (size_t)m * 512 + half * 256 + ch * 16 + (const char*)0;
            CP_ASYNC(sbase + soff,          As + (size_t)(g - (const char*)0));
            CP_ASYNC(sbase + 16384 + soff,  Bs + (size_t)(g - (const char*)0));
        }
    };

    load_stage(0, 0);
    CP_COMMIT();

    for (int kc = 0; kc < 4; ++kc) {
        CP_WAIT0();
        __syncthreads();
        if (kc < 3) { load_stage(kc + 1, (kc + 1) & 1); CP_COMMIT(); }

        uint32_t st = sb + (uint32_t)(kc & 1) * STAGE_B;

#pragma unroll
        for (int ks = 0; ks < 2; ++ks) {         // k offsets 0, 16 within chunk
            const int ch = ks * 2 + hi2;         // lane's 16B chunk (0..3)

            uint32_t ah[4][4], al[4][4];
#pragma unroll
            for (int mt = 0; mt < 4; ++mt) {
                int m = wm * 64 + mt * 16 + lo16;
                uint32_t sw = (uint32_t)((m * 4 + (ch ^ ((m >> 1) & 3))) << 4);
                LDSM4(ah[mt], st + sw);
                LDSM4(al[mt], st + 8192 + sw);
            }

            uint32_t bb[2][4];
#pragma unroll
            for (int np = 0; np < 2; ++np) {
                int n = wn * 32 + np * 16 + lo16;
                uint32_t sw = (uint32_t)((n * 4 + (ch ^ ((n >> 1) & 3))) << 4);
                LDSM4(bb[np], st + 16384 + sw);   // B_hi
            }
#pragma unroll
            for (int mt = 0; mt < 4; ++mt)
#pragma unroll
                for (int nt = 0; nt < 4; ++nt)
                    MMA(acc[mt][nt], ah[mt], bb[nt >> 1][nt & 1], bb[nt >> 1][2 + (nt & 1)]);
#pragma unroll
            for (int mt = 0; mt < 4; ++mt)
#pragma unroll
                for (int nt = 0; nt < 4; ++nt)
                    MMA(acc[mt][nt], al[mt], bb[nt >> 1][nt & 1], bb[nt >> 1][2 + (nt & 1)]);

#pragma unroll
            for (int np = 0; np < 2; ++np) {
                int n = wn * 32 + np * 16 + lo16;
                uint32_t sw = (uint32_t)((n * 4 + (ch ^ ((n >> 1) & 3))) << 4);
                LDSM4(bb[np], st + 24576 + sw);   // B_lo
            }
#pragma unroll
            for (int mt = 0; mt < 4; ++mt)
#pragma unroll
                for (int nt = 0; nt < 4; ++nt)
                    MMA(acc[mt][nt], ah[mt], bb[nt >> 1][nt & 1], bb[nt >> 1][2 + (nt & 1)]);
        }
        __syncthreads();
    }

    // ---- epilogue: direct fp32 float2 stores ----
    float* op = out + (size_t)pr * (HW * HW);
    const int g = l >> 2, tg = l & 3;
#pragma unroll
    for (int mt = 0; mt < 4; ++mt) {
#pragma unroll
        for (int nt = 0; nt < 4; ++nt) {
            int row = p0 + wm * 64 + mt * 16 + g;
            int col = q0 + wn * 32 + nt * 8 + tg * 2;
            *(float2*)&op[(size_t)row * HW + col] =
                make_float2(acc[mt][nt][0], acc[mt][nt][1]);
            *(float2*)&op[(size_t)(row + 8) * HW + col] =
                make_float2(acc[mt][nt][2], acc[mt][nt][3]);
        }
    }
}

// ---------------------------------------------------------------------------
extern "C" void kernel_launch(void* const* d_in, const int* in_sizes, int n_in,
                              void* d_out, int out_size) {
    const float* x = (const float*)d_in[0];
    float* out = (float*)d_out;

    norm_split_kernel<<<128, 256>>>(x);

    cudaFuncSetAttribute(corr_gemm2, cudaFuncAttributeMaxDynamicSharedMemorySize, 2 * STAGE_B);
    dim3 grid(8, 8, 96);
    corr_gemm2<<<grid, 256, 2 * STAGE_B>>>(out);
}

// round 7
// speedup vs baseline: 3.0397x; 1.4762x over previous
#include <cuda_runtime.h>
#include <cuda_bf16.h>
#include <cstdint>

#define HW   1024
#define CD   128
#define EPSF 1e-8f

// Normalized features, bf16 hi/lo split, pixel-major:
// g_feat[view][p][0..127]=hi, [128..255]=lo   (512 B per pixel row)
__device__ __nv_bfloat16 g_feat[32 * HW * 256];

// ---------------------------------------------------------------------------
__device__ __forceinline__ uint32_t smem_u32(const void* p) {
    uint32_t a;
    asm("{ .reg .u64 t; cvta.to.shared.u64 t, %1; cvt.u32.u64 %0, t; }" : "=r"(a) : "l"(p));
    return a;
}

#define CP_ASYNC(s, g) \
    asm volatile("cp.async.cg.shared.global [%0], [%1], 16;" :: "r"(s), "l"(g))
#define CP_COMMIT() asm volatile("cp.async.commit_group;" ::: "memory")
#define CP_WAIT0()  asm volatile("cp.async.wait_group 0;" ::: "memory")

#define LDSM4(r, a) \
    asm volatile("ldmatrix.sync.aligned.m8n8.x4.shared.b16 {%0,%1,%2,%3}, [%4];" \
        : "=r"((r)[0]), "=r"((r)[1]), "=r"((r)[2]), "=r"((r)[3]) : "r"(a))

#define MMA(d, a, b0v, b1v)                                                  \
    asm volatile(                                                            \
        "mma.sync.aligned.m16n8k16.row.col.f32.bf16.bf16.f32 "               \
        "{%0,%1,%2,%3}, {%4,%5,%6,%7}, {%8,%9}, {%0,%1,%2,%3};\n"            \
        : "+f"((d)[0]), "+f"((d)[1]), "+f"((d)[2]), "+f"((d)[3])             \
        : "r"((a)[0]), "r"((a)[1]), "r"((a)[2]), "r"((a)[3]),                \
          "r"(b0v), "r"(b1v))

// ---------------------------------------------------------------------------
// Kernel 1: L2-normalize per pixel, split to bf16 hi/lo, write pixel-major
// ---------------------------------------------------------------------------
__global__ __launch_bounds__(256) void norm_split_kernel(const float* __restrict__ x) {
    __shared__ uint32_t tile[8][33 * 32];
    int w = threadIdx.x >> 5, l = threadIdx.x & 31;
    int gp = blockIdx.x * 256 + w * 32 + l;        // global pixel over 32 views
    int view = gp >> 10, p = gp & 1023;
    const float* xp = x + (size_t)view * (CD * HW) + p;

    float s = 0.f;
#pragma unroll 8
    for (int c = 0; c < CD; ++c) { float v = xp[c << 10]; s += v * v; }
    float inv = 1.f / (sqrtf(s) + EPSF);

    __nv_bfloat16* ob = g_feat + (size_t)(gp - l) * 256;   // warp's base pixel row

    for (int cb = 0; cb < 4; ++cb) {
#pragma unroll
        for (int ci = 0; ci < 32; ++ci) {
            float v = xp[(cb * 32 + ci) << 10] * inv;
            __nv_bfloat16 h = __float2bfloat16(v);
            __nv_bfloat16 lo = __float2bfloat16(v - __bfloat162float(h));
            tile[w][ci * 33 + l] = (uint32_t)__bfloat16_as_ushort(h)
                                 | ((uint32_t)__bfloat16_as_ushort(lo) << 16);
        }
        __syncwarp();
#pragma unroll
        for (int rr = 0; rr < 32; ++rr) {
            uint32_t v = tile[w][l * 33 + rr];
            __nv_bfloat16* row = ob + (size_t)rr * 256 + cb * 32 + l;
            row[0]   = __ushort_as_bfloat16((unsigned short)(v & 0xFFFF));
            row[128] = __ushort_as_bfloat16((unsigned short)(v >> 16));
        }
        __syncwarp();
    }
}

// ---------------------------------------------------------------------------
// Kernel 2: HMMA GEMM over the 48 UNIQUE view pairs (i<j); each CTA computes
// G = f_j^T f_i tile (128x128) and writes it twice: direct to out[idx1] and
// transposed (via swizzled smem) to out[idx2].  CTA tile 128x128, warp 64x32.
// Smem stage (32KB): [A_hi 8K][A_lo 8K][B_hi 8K][B_lo 8K]; 2-stage cp.async.
// ---------------------------------------------------------------------------
#define STAGE_B 32768

__constant__ int c_pi[6] = {0, 0, 0, 1, 1, 2};
__constant__ int c_pj[6] = {1, 2, 3, 2, 3, 3};

__global__ __launch_bounds__(256, 2) void corr_gemm3(float* __restrict__ out) {
    extern __shared__ char smem[];
    uint32_t sb = smem_u32(smem);
    const int tid = threadIdx.x;
    const int w = tid >> 5, l = tid & 31;
    const int wm = w >> 2, wn = w & 3;          // warp grid 2x4
    const int lo16 = l & 15, hi2 = l >> 4;

    const int q0 = blockIdx.x * 128;
    const int p0 = blockIdx.y * 128;
    const int z  = blockIdx.z;                  // 0..47
    const int b  = z / 6, u = z % 6;
    const int i  = c_pi[u], j = c_pj[u];
    const int idx1 = b * 12 + i * 3 + (j - 1);  // A=f_j rows, B=f_i cols
    const int idx2 = b * 12 + j * 3 + i;        // transposed twin

    const char* Af = (const char*)g_feat + (size_t)(b * 4 + j) * HW * 512 + (size_t)p0 * 512;
    const char* Bf = (const char*)g_feat + (size_t)(b * 4 + i) * HW * 512 + (size_t)q0 * 512;

    float acc[4][4][4];
#pragma unroll
    for (int mt = 0; mt < 4; ++mt)
#pragma unroll
        for (int nt = 0; nt < 4; ++nt)
#pragma unroll
            for (int e = 0; e < 4; ++e) acc[mt][nt][e] = 0.f;

    // ---- stage loader: 2048 16B chunks (A+B, hi+lo), 8 per thread ----
    auto load_stage = [&](int kc, int st) {
        uint32_t sbase = sb + st * STAGE_B;
        const char* As = Af + kc * 64;
        const char* Bs = Bf + kc * 64;
#pragma unroll
        for (int it = 0; it < 4; ++it) {
            int c = it * 256 + tid;
            int m = c >> 3, half = (c >> 2) & 1, ch = c & 3;
            uint32_t soff = half * 8192u + (uint32_t)((m * 4 + (ch ^ ((m >> 1) & 3))) << 4);
            size_t goff = (size_t)m * 512 + half * 256 + ch * 16;
            CP_ASYNC(sbase + soff,         As + goff);
            CP_ASYNC(sbase + 16384 + soff, Bs + goff);
        }
    };

    load_stage(0, 0);
    CP_COMMIT();

    for (int kc = 0; kc < 4; ++kc) {
        CP_WAIT0();
        __syncthreads();
        if (kc < 3) { load_stage(kc + 1, (kc + 1) & 1); CP_COMMIT(); }

        uint32_t st = sb + (uint32_t)(kc & 1) * STAGE_B;

#pragma unroll
        for (int ks = 0; ks < 2; ++ks) {         // k offsets 0, 16 within chunk
            const int ch = ks * 2 + hi2;         // lane's 16B chunk (0..3)

            uint32_t ah[4][4], al[4][4];
#pragma unroll
            for (int mt = 0; mt < 4; ++mt) {
                int m = wm * 64 + mt * 16 + lo16;
                uint32_t sw = (uint32_t)((m * 4 + (ch ^ ((m >> 1) & 3))) << 4);
                LDSM4(ah[mt], st + sw);
                LDSM4(al[mt], st + 8192 + sw);
            }

            uint32_t bb[2][4];
#pragma unroll
            for (int np = 0; np < 2; ++np) {
                int n = wn * 32 + np * 16 + lo16;
                uint32_t sw = (uint32_t)((n * 4 + (ch ^ ((n >> 1) & 3))) << 4);
                LDSM4(bb[np], st + 16384 + sw);   // B_hi
            }
#pragma unroll
            for (int mt = 0; mt < 4; ++mt)
#pragma unroll
                for (int nt = 0; nt < 4; ++nt)
                    MMA(acc[mt][nt], ah[mt], bb[nt >> 1][nt & 1], bb[nt >> 1][2 + (nt & 1)]);
#pragma unroll
            for (int mt = 0; mt < 4; ++mt)
#pragma unroll
                for (int nt = 0; nt < 4; ++nt)
                    MMA(acc[mt][nt], al[mt], bb[nt >> 1][nt & 1], bb[nt >> 1][2 + (nt & 1)]);

#pragma unroll
            for (int np = 0; np < 2; ++np) {
                int n = wn * 32 + np * 16 + lo16;
                uint32_t sw = (uint32_t)((n * 4 + (ch ^ ((n >> 1) & 3))) << 4);
                LDSM4(bb[np], st + 24576 + sw);   // B_lo
            }
#pragma unroll
            for (int mt = 0; mt < 4; ++mt)
#pragma unroll
                for (int nt = 0; nt < 4; ++nt)
                    MMA(acc[mt][nt], ah[mt], bb[nt >> 1][nt & 1], bb[nt >> 1][2 + (nt & 1)]);
        }
        __syncthreads();
    }

    const int g = l >> 2, tg = l & 3;

    // ---- epilogue 1: direct fp32 float2 stores to out[idx1] ----
    {
        float* op = out + (size_t)idx1 * (HW * HW);
#pragma unroll
        for (int mt = 0; mt < 4; ++mt) {
#pragma unroll
            for (int nt = 0; nt < 4; ++nt) {
                int row = p0 + wm * 64 + mt * 16 + g;
                int col = q0 + wn * 32 + nt * 8 + tg * 2;
                *(float2*)&op[(size_t)row * HW + col] =
                    make_float2(acc[mt][nt][0], acc[mt][nt][1]);
                *(float2*)&op[(size_t)(row + 8) * HW + col] =
                    make_float2(acc[mt][nt][2], acc[mt][nt][3]);
            }
        }
    }

    // ---- epilogue 2: transposed tile to out[idx2] via swizzled smem ----
    // per-warp 8KB region: G[n][m] stored at float index n*64 + (m ^ ((n&6)<<2))
    {
        float* tw = (float*)smem + w * 2048;
#pragma unroll
        for (int mt = 0; mt < 4; ++mt)
#pragma unroll
            for (int nt = 0; nt < 4; ++nt)
#pragma unroll
                for (int e = 0; e < 4; ++e) {
                    int n = nt * 8 + tg * 2 + (e & 1);
                    int m = mt * 16 + g + 8 * (e >> 1);
                    tw[n * 64 + (m ^ ((n & 6) << 2))] = acc[mt][nt][e];
                }
        __syncwarp();

        float* op = out + (size_t)idx2 * (HW * HW);
        const float2* tw2 = (const float2*)tw;
#pragma unroll
        for (int n = 0; n < 32; ++n) {
            float2 v = tw2[n * 32 + (l ^ ((n & 6) << 1))];   // = (G[n][2l], G[n][2l+1])
            *(float2*)&op[(size_t)(q0 + wn * 32 + n) * HW + p0 + wm * 64 + 2 * l] = v;
        }
    }
}

// ---------------------------------------------------------------------------
extern "C" void kernel_launch(void* const* d_in, const int* in_sizes, int n_in,
                              void* d_out, int out_size) {
    const float* x = (const float*)d_in[0];
    float* out = (float*)d_out;

    norm_split_kernel<<<128, 256>>>(x);

    cudaFuncSetAttribute(corr_gemm3, cudaFuncAttributeMaxDynamicSharedMemorySize, 2 * STAGE_B);
    dim3 grid(8, 8, 48);
    corr_gemm3<<<grid, 256, 2 * STAGE_B>>>(out);
}